// round 13
// baseline (speedup 1.0000x reference)
#include <cuda_runtime.h>
#include <cuda_fp16.h>

#define NN 100000
#define DF 16

// ---- device scratch (no allocations allowed) ----
__device__ float g_D[NN * DF];                      // diag sums, fp32 (rarely hit)
__device__ __align__(16) __half2 g_PrS_h[NN * 8];   // row sums, fp16 (32B/node)
__device__ __align__(16) __half2 g_PcS_h[NN * 8];   // col sums, fp16
__device__ int   g_rcnt[NN];
__device__ int   g_ccnt[NN];
// fp16 broadcast tables: 16 halves (32B) per node
// rowb' includes (all_scalar + bias0); diagb' includes (diag_scalar + bias1)
__device__ __align__(16) __half2 g_rowb_h[NN * 8];
__device__ __align__(16) __half2 g_colb_h[NN * 8];
__device__ __align__(16) __half2 g_diagb_h[NN * 8];
__device__ float g_pdsum[DF];
__device__ float g_pasum[DF];

__device__ __forceinline__ void red4(float* p, float4 v) {
    asm volatile("red.global.add.v4.f32 [%0], {%1,%2,%3,%4};"
                 :: "l"(p), "f"(v.x), "f"(v.y), "f"(v.z), "f"(v.w) : "memory");
}
__device__ __forceinline__ void red4h(__half2* p, unsigned a, unsigned b,
                                      unsigned c, unsigned d) {
    asm volatile("red.global.add.noftz.v4.f16x2 [%0], {%1,%2,%3,%4};"
                 :: "l"(p), "r"(a), "r"(b), "r"(c), "r"(d) : "memory");
}

// ---- K0: zero scratch ----
__global__ void k_zero() {
    int tid = blockIdx.x * blockDim.x + threadIdx.x;
    int stride = gridDim.x * blockDim.x;
    float4 z = make_float4(0.f, 0.f, 0.f, 0.f);
    uint4 zu = make_uint4(0, 0, 0, 0);
    for (int t = tid; t < NN * 4; t += stride) ((float4*)g_D)[t] = z;
    for (int t = tid; t < NN * 2; t += stride) {
        ((uint4*)g_PrS_h)[t] = zu;
        ((uint4*)g_PcS_h)[t] = zu;
    }
    for (int t = tid; t < NN; t += stride) { g_rcnt[t] = 0; g_ccnt[t] = 0; }
    if (blockIdx.x == 0 && threadIdx.x < DF) {
        g_pdsum[threadIdx.x] = 0.f; g_pasum[threadIdx.x] = 0.f;
    }
}

// ---- K1: pooling pass (fp16 vector REDs for Pr/Pc) ----
__global__ void __launch_bounds__(256) k_pool(
    const float* __restrict__ vals, const int* __restrict__ row,
    const int* __restrict__ col, int nnz)
{
    __shared__ float s_pa[DF], s_pd[DF];
    if (threadIdx.x < DF) { s_pa[threadIdx.x] = 0.f; s_pd[threadIdx.x] = 0.f; }
    __syncthreads();

    float pa[DF], pd[DF];
#pragma unroll
    for (int k = 0; k < DF; k++) { pa[k] = 0.f; pd[k] = 0.f; }

    int tid = blockIdx.x * blockDim.x + threadIdx.x;
    int stride = gridDim.x * blockDim.x;
    for (int i = tid; i < nnz; i += stride) {
        int r = row[i], c = col[i];
        const float4* vp = (const float4*)(vals + (size_t)i * DF);
        float4 v0 = vp[0], v1 = vp[1], v2 = vp[2], v3 = vp[3];

        __half2 hv[8];
        hv[0] = __floats2half2_rn(v0.x, v0.y); hv[1] = __floats2half2_rn(v0.z, v0.w);
        hv[2] = __floats2half2_rn(v1.x, v1.y); hv[3] = __floats2half2_rn(v1.z, v1.w);
        hv[4] = __floats2half2_rn(v2.x, v2.y); hv[5] = __floats2half2_rn(v2.z, v2.w);
        hv[6] = __floats2half2_rn(v3.x, v3.y); hv[7] = __floats2half2_rn(v3.z, v3.w);
        const unsigned* hu = (const unsigned*)hv;

        __half2* pr = g_PrS_h + (size_t)r * 8;
        red4h(pr + 0, hu[0], hu[1], hu[2], hu[3]);
        red4h(pr + 4, hu[4], hu[5], hu[6], hu[7]);
        __half2* pc = g_PcS_h + (size_t)c * 8;
        red4h(pc + 0, hu[0], hu[1], hu[2], hu[3]);
        red4h(pc + 4, hu[4], hu[5], hu[6], hu[7]);
        atomicAdd(&g_rcnt[r], 1);
        atomicAdd(&g_ccnt[c], 1);

        pa[0]  += v0.x; pa[1]  += v0.y; pa[2]  += v0.z; pa[3]  += v0.w;
        pa[4]  += v1.x; pa[5]  += v1.y; pa[6]  += v1.z; pa[7]  += v1.w;
        pa[8]  += v2.x; pa[9]  += v2.y; pa[10] += v2.z; pa[11] += v2.w;
        pa[12] += v3.x; pa[13] += v3.y; pa[14] += v3.z; pa[15] += v3.w;

        if (r == c) {
            float* dd = &g_D[(size_t)r * DF];
            red4(dd + 0, v0); red4(dd + 4, v1); red4(dd + 8, v2); red4(dd + 12, v3);
            pd[0]  += v0.x; pd[1]  += v0.y; pd[2]  += v0.z; pd[3]  += v0.w;
            pd[4]  += v1.x; pd[5]  += v1.y; pd[6]  += v1.z; pd[7]  += v1.w;
            pd[8]  += v2.x; pd[9]  += v2.y; pd[10] += v2.z; pd[11] += v2.w;
            pd[12] += v3.x; pd[13] += v3.y; pd[14] += v3.z; pd[15] += v3.w;
        }
    }

#pragma unroll
    for (int k = 0; k < DF; k++) {
#pragma unroll
        for (int o = 16; o > 0; o >>= 1) {
            pa[k] += __shfl_down_sync(0xffffffffu, pa[k], o);
            pd[k] += __shfl_down_sync(0xffffffffu, pd[k], o);
        }
    }
    if ((threadIdx.x & 31) == 0) {
#pragma unroll
        for (int k = 0; k < DF; k++) {
            atomicAdd(&s_pa[k], pa[k]);
            atomicAdd(&s_pd[k], pd[k]);
        }
    }
    __syncthreads();
    if (threadIdx.x < DF) {
        atomicAdd(&g_pasum[threadIdx.x], s_pa[threadIdx.x]);
        atomicAdd(&g_pdsum[threadIdx.x], s_pd[threadIdx.x]);
    }
}

// unpack a uint4 (8 halves) into f[8]
__device__ __forceinline__ void h8_to_f(const uint4& u, float* f) {
    const unsigned* p = &u.x;
#pragma unroll
    for (int i = 0; i < 4; i++) {
        float2 t = __half22float2(*(const __half2*)&p[i]);
        f[i * 2 + 0] = t.x; f[i * 2 + 1] = t.y;
    }
}
// load 4 fp16 weights from shared, convert to fp32
__device__ __forceinline__ void ldw4(const __half* base, int idx, float* out) {
    uint2 u = *(const uint2*)(base + idx);
    float2 a = __half22float2(*(const __half2*)&u.x);
    float2 b = __half22float2(*(const __half2*)&u.y);
    out[0] = a.x; out[1] = a.y; out[2] = b.x; out[3] = b.y;
}

// ---- K2: per-node broadcast vectors; scalar terms folded into tables ----
__global__ void __launch_bounds__(256) k_node(const float* __restrict__ W,
                                              const float* __restrict__ bias,
                                              int nnz) {
    __shared__ __half sWh[9 * DF * DF];  // W2..W10 as fp16
    __shared__ float s_call[DF], s_cdiag[DF];
    for (int t = threadIdx.x; t < 9 * DF * DF; t += blockDim.x)
        sWh[t] = __float2half(W[2 * DF * DF + t]);
    if (threadIdx.x < DF) {
        int k = threadIdx.x;
        float inv_n = 1.f / (float)NN;
        float inv_e = 1.f / (float)nnz;
        float ds = 0.f, as = 0.f;
#pragma unroll
        for (int j = 0; j < DF; j++) {
            float pdj = g_pdsum[j] * inv_n;
            float paj = g_pasum[j] * inv_e;
            ds += pdj * W[11 * 256 + j * DF + k] + paj * W[13 * 256 + j * DF + k];
            as += pdj * W[12 * 256 + j * DF + k] + paj * W[14 * 256 + j * DF + k];
        }
        s_call[k]  = as + bias[k];        // folded into rowb
        s_cdiag[k] = ds + bias[DF + k];   // folded into diagb
    }
    __syncthreads();

    int gid = blockIdx.x * blockDim.x + threadIdx.x;
    int n = gid >> 2;
    int q = (gid & 3) * 4;
    if (n >= NN) return;

    float rinv = 1.f / (float)max(g_rcnt[n], 1);
    float cinv = 1.f / (float)max(g_ccnt[n], 1);

    float dv[DF], prv[DF], pcv[DF];
    {
        const float4* dp  = (const float4*)&g_D[(size_t)n * DF];
        *(float4*)&dv[0]  = dp[0];  *(float4*)&dv[4]  = dp[1];
        *(float4*)&dv[8]  = dp[2];  *(float4*)&dv[12] = dp[3];
        const uint4* prp = (const uint4*)(g_PrS_h + (size_t)n * 8);
        const uint4* pcp = (const uint4*)(g_PcS_h + (size_t)n * 8);
        uint4 a = prp[0], b = prp[1], cgl = pcp[0], d = pcp[1];
        h8_to_f(a, &prv[0]); h8_to_f(b, &prv[8]);
        h8_to_f(cgl, &pcv[0]); h8_to_f(d, &pcv[8]);
    }
#pragma unroll
    for (int k = 0; k < DF; k++) { prv[k] *= rinv; pcv[k] *= cinv; }

    float db[4], rb[4], cb[4];
#pragma unroll
    for (int t = 0; t < 4; t++) {
        db[t] = s_cdiag[q + t];   // scalar fold
        rb[t] = s_call[q + t];    // scalar fold
        cb[t] = 0.f;
    }

#pragma unroll
    for (int j = 0; j < DF; j++) {
        float d = dv[j], pr = prv[j], pc = pcv[j];
        float w2[4], w3[4], w4[4], w5[4], w6[4], w7[4], w8[4], w9[4], wa[4];
        ldw4(sWh, (0 * DF + j) * DF + q, w2);
        ldw4(sWh, (1 * DF + j) * DF + q, w3);
        ldw4(sWh, (2 * DF + j) * DF + q, w4);
        ldw4(sWh, (3 * DF + j) * DF + q, w5);
        ldw4(sWh, (4 * DF + j) * DF + q, w6);
        ldw4(sWh, (5 * DF + j) * DF + q, w7);
        ldw4(sWh, (6 * DF + j) * DF + q, w8);
        ldw4(sWh, (7 * DF + j) * DF + q, w9);
        ldw4(sWh, (8 * DF + j) * DF + q, wa);
#pragma unroll
        for (int t = 0; t < 4; t++) {
            db[t] += d * w2[t] + pr * w5[t] + pc * w8[t];
            rb[t] += d * w3[t] + pr * w6[t] + pc * w9[t];
            cb[t] += d * w4[t] + pr * w7[t] + pc * wa[t];
        }
    }

    int hidx = n * 8 + (q >> 1);
    __half2 d0 = __floats2half2_rn(db[0], db[1]);
    __half2 d1 = __floats2half2_rn(db[2], db[3]);
    __half2 r0 = __floats2half2_rn(rb[0], rb[1]);
    __half2 r1 = __floats2half2_rn(rb[2], rb[3]);
    __half2 c0 = __floats2half2_rn(cb[0], cb[1]);
    __half2 c1 = __floats2half2_rn(cb[2], cb[3]);
    *(uint2*)&g_diagb_h[hidx] = make_uint2(*(unsigned*)&d0, *(unsigned*)&d1);
    *(uint2*)&g_rowb_h[hidx]  = make_uint2(*(unsigned*)&r0, *(unsigned*)&r1);
    *(uint2*)&g_colb_h[hidx]  = make_uint2(*(unsigned*)&c0, *(unsigned*)&c1);
}

// ---- K3: main per-entry pass, PAIR layout (scalars pre-folded) ----
__global__ void __launch_bounds__(256, 6) k_main(
    const float* __restrict__ vals, const int* __restrict__ row,
    const int* __restrict__ col, const float* __restrict__ W,
    float* __restrict__ Y, int nnz)
{
    __shared__ float sW0[DF * DF];
    sW0[threadIdx.x] = W[threadIdx.x];  // blockDim == 256
    __syncthreads();

    int gid = blockIdx.x * blockDim.x + threadIdx.x;
    int e = gid >> 1;
    if (e >= nnz) return;
    int h = gid & 1;
    int hb = h * 8;
    unsigned mask = __activemask();

    int r = row[e], c = col[e];

    float vo[8];
    {
        const float4* vp = (const float4*)(vals + (size_t)e * DF + hb);
        *(float4*)&vo[0] = vp[0]; *(float4*)&vo[4] = vp[1];
    }
    uint4 rbu = ((const uint4*)(g_rowb_h + (size_t)r * 8))[h];
    uint4 cbu = ((const uint4*)(g_colb_h + (size_t)c * 8))[h];

    float y[8], tmp[8];
    h8_to_f(rbu, y);          // rowb' already contains all_scalar + bias0
    h8_to_f(cbu, tmp);
#pragma unroll
    for (int k = 0; k < 8; k++) y[k] += tmp[k];

    if (r == c) {
        uint4 dbu = ((const uint4*)(g_diagb_h + (size_t)r * 8))[h];
        h8_to_f(dbu, tmp);    // diagb' already contains diag_scalar + bias1
#pragma unroll
        for (int k = 0; k < 8; k++) y[k] += tmp[k];
    }

    float vx[8];
#pragma unroll
    for (int k = 0; k < 8; k++) vx[k] = __shfl_xor_sync(mask, vo[k], 1);
    float vf[DF];
#pragma unroll
    for (int k = 0; k < 8; k++) {
        vf[k]     = h ? vx[k] : vo[k];
        vf[8 + k] = h ? vo[k] : vx[k];
    }

#pragma unroll
    for (int j = 0; j < DF; j++) {
        float vj = vf[j];
        float4 wA = *(const float4*)&sW0[j * DF + hb];
        float4 wB = *(const float4*)&sW0[j * DF + hb + 4];
        y[0] += vj * wA.x; y[1] += vj * wA.y; y[2] += vj * wA.z; y[3] += vj * wA.w;
        y[4] += vj * wB.x; y[5] += vj * wB.y; y[6] += vj * wB.z; y[7] += vj * wB.w;
    }

    float4* yo = (float4*)(Y + (size_t)e * DF + hb);
    yo[0] = *(float4*)&y[0]; yo[1] = *(float4*)&y[4];
}

// ---- K4: transpose scatter-add, PAIR layout (fp32 vals gather) ----
__global__ void __launch_bounds__(256, 6) k_trans(
    const float* __restrict__ vals, const int* __restrict__ tin,
    const int* __restrict__ tout, const float* __restrict__ W,
    float* __restrict__ Y, int nnzt)
{
    __shared__ float sW1[DF * DF];
    sW1[threadIdx.x] = W[DF * DF + threadIdx.x];  // W[1], blockDim == 256
    __syncthreads();

    int gid = blockIdx.x * blockDim.x + threadIdx.x;
    int t = gid >> 1;
    if (t >= nnzt) return;
    int h = gid & 1;
    int hb = h * 8;
    unsigned mask = __activemask();

    int ii = tin[t], io = tout[t];

    float vo[8];
    {
        const float4* vp = (const float4*)(vals + (size_t)ii * DF + hb);
        *(float4*)&vo[0] = vp[0]; *(float4*)&vo[4] = vp[1];
    }
    float vx[8];
#pragma unroll
    for (int k = 0; k < 8; k++) vx[k] = __shfl_xor_sync(mask, vo[k], 1);
    float vf[DF];
#pragma unroll
    for (int k = 0; k < 8; k++) {
        vf[k]     = h ? vx[k] : vo[k];
        vf[8 + k] = h ? vo[k] : vx[k];
    }

    float g[8];
#pragma unroll
    for (int k = 0; k < 8; k++) g[k] = 0.f;
#pragma unroll
    for (int j = 0; j < DF; j++) {
        float vj = vf[j];
        float4 wA = *(const float4*)&sW1[j * DF + hb];
        float4 wB = *(const float4*)&sW1[j * DF + hb + 4];
        g[0] += vj * wA.x; g[1] += vj * wA.y; g[2] += vj * wA.z; g[3] += vj * wA.w;
        g[4] += vj * wB.x; g[5] += vj * wB.y; g[6] += vj * wB.z; g[7] += vj * wB.w;
    }

    float* yp = Y + (size_t)io * DF + hb;
    red4(yp + 0, make_float4(g[0], g[1], g[2], g[3]));
    red4(yp + 4, make_float4(g[4], g[5], g[6], g[7]));
}

extern "C" void kernel_launch(void* const* d_in, const int* in_sizes, int n_in,
                              void* d_out, int out_size) {
    const float* vals = (const float*)d_in[0];
    const float* W    = (const float*)d_in[1];
    const float* bias = (const float*)d_in[2];
    const int* row    = (const int*)d_in[3];
    const int* col    = (const int*)d_in[4];
    const int* tin    = (const int*)d_in[5];
    const int* tout   = (const int*)d_in[6];
    float* Y = (float*)d_out;

    int nnz  = in_sizes[0] / DF;
    int nnzt = in_sizes[5];

    k_zero<<<1024, 256>>>();
    k_pool<<<2368, 256>>>(vals, row, col, nnz);
    k_node<<<(NN * 4 + 255) / 256, 256>>>(W, bias, nnz);
    k_main<<<(nnz * 2 + 255) / 256, 256>>>(vals, row, col, W, Y, nnz);
    k_trans<<<(nnzt * 2 + 255) / 256, 256>>>(vals, tin, tout, W, Y, nnzt);
}

// round 15
// speedup vs baseline: 1.0198x; 1.0198x over previous
#include <cuda_runtime.h>
#include <cuda_fp16.h>

#define NN 100000
#define DF 16

// ---- device scratch (no allocations allowed) ----
__device__ float g_D[NN * DF];                      // diag sums, fp32 (rarely hit)
__device__ __align__(16) __half2 g_PrS_h[NN * 8];   // row sums, fp16 (32B/node)
__device__ __align__(16) __half2 g_PcS_h[NN * 8];   // col sums, fp16
__device__ int   g_rcnt[NN];
__device__ int   g_ccnt[NN];
// fp16 broadcast tables: 16 halves (32B) per node
__device__ __align__(16) __half2 g_rowb_h[NN * 8];
__device__ __align__(16) __half2 g_colb_h[NN * 8];
__device__ __align__(16) __half2 g_diagb_h[NN * 8];
__device__ float g_pdsum[DF];
__device__ float g_pasum[DF];
__device__ float g_call[DF];   // all_scalar + bias[0]
__device__ float g_cdiag[DF];  // diag_scalar + bias[1]

__device__ __forceinline__ void red4(float* p, float4 v) {
    asm volatile("red.global.add.v4.f32 [%0], {%1,%2,%3,%4};"
                 :: "l"(p), "f"(v.x), "f"(v.y), "f"(v.z), "f"(v.w) : "memory");
}
__device__ __forceinline__ void red4h(__half2* p, unsigned a, unsigned b,
                                      unsigned c, unsigned d) {
    asm volatile("red.global.add.noftz.v4.f16x2 [%0], {%1,%2,%3,%4};"
                 :: "l"(p), "r"(a), "r"(b), "r"(c), "r"(d) : "memory");
}

// ---- K0: zero scratch ----
__global__ void k_zero() {
    int tid = blockIdx.x * blockDim.x + threadIdx.x;
    int stride = gridDim.x * blockDim.x;
    float4 z = make_float4(0.f, 0.f, 0.f, 0.f);
    uint4 zu = make_uint4(0, 0, 0, 0);
    for (int t = tid; t < NN * 4; t += stride) ((float4*)g_D)[t] = z;
    for (int t = tid; t < NN * 2; t += stride) {
        ((uint4*)g_PrS_h)[t] = zu;
        ((uint4*)g_PcS_h)[t] = zu;
    }
    for (int t = tid; t < NN; t += stride) { g_rcnt[t] = 0; g_ccnt[t] = 0; }
    if (blockIdx.x == 0 && threadIdx.x < DF) {
        g_pdsum[threadIdx.x] = 0.f; g_pasum[threadIdx.x] = 0.f;
    }
}

// ---- K1: pooling pass (fp16 vector REDs for Pr/Pc) ----
__global__ void __launch_bounds__(256) k_pool(
    const float* __restrict__ vals, const int* __restrict__ row,
    const int* __restrict__ col, int nnz)
{
    __shared__ float s_pa[DF], s_pd[DF];
    if (threadIdx.x < DF) { s_pa[threadIdx.x] = 0.f; s_pd[threadIdx.x] = 0.f; }
    __syncthreads();

    float pa[DF], pd[DF];
#pragma unroll
    for (int k = 0; k < DF; k++) { pa[k] = 0.f; pd[k] = 0.f; }

    int tid = blockIdx.x * blockDim.x + threadIdx.x;
    int stride = gridDim.x * blockDim.x;
    for (int i = tid; i < nnz; i += stride) {
        int r = row[i], c = col[i];
        const float4* vp = (const float4*)(vals + (size_t)i * DF);
        float4 v0 = vp[0], v1 = vp[1], v2 = vp[2], v3 = vp[3];

        __half2 hv[8];
        hv[0] = __floats2half2_rn(v0.x, v0.y); hv[1] = __floats2half2_rn(v0.z, v0.w);
        hv[2] = __floats2half2_rn(v1.x, v1.y); hv[3] = __floats2half2_rn(v1.z, v1.w);
        hv[4] = __floats2half2_rn(v2.x, v2.y); hv[5] = __floats2half2_rn(v2.z, v2.w);
        hv[6] = __floats2half2_rn(v3.x, v3.y); hv[7] = __floats2half2_rn(v3.z, v3.w);
        const unsigned* hu = (const unsigned*)hv;

        __half2* pr = g_PrS_h + (size_t)r * 8;
        red4h(pr + 0, hu[0], hu[1], hu[2], hu[3]);
        red4h(pr + 4, hu[4], hu[5], hu[6], hu[7]);
        __half2* pc = g_PcS_h + (size_t)c * 8;
        red4h(pc + 0, hu[0], hu[1], hu[2], hu[3]);
        red4h(pc + 4, hu[4], hu[5], hu[6], hu[7]);
        atomicAdd(&g_rcnt[r], 1);
        atomicAdd(&g_ccnt[c], 1);

        pa[0]  += v0.x; pa[1]  += v0.y; pa[2]  += v0.z; pa[3]  += v0.w;
        pa[4]  += v1.x; pa[5]  += v1.y; pa[6]  += v1.z; pa[7]  += v1.w;
        pa[8]  += v2.x; pa[9]  += v2.y; pa[10] += v2.z; pa[11] += v2.w;
        pa[12] += v3.x; pa[13] += v3.y; pa[14] += v3.z; pa[15] += v3.w;

        if (r == c) {
            float* dd = &g_D[(size_t)r * DF];
            red4(dd + 0, v0); red4(dd + 4, v1); red4(dd + 8, v2); red4(dd + 12, v3);
            pd[0]  += v0.x; pd[1]  += v0.y; pd[2]  += v0.z; pd[3]  += v0.w;
            pd[4]  += v1.x; pd[5]  += v1.y; pd[6]  += v1.z; pd[7]  += v1.w;
            pd[8]  += v2.x; pd[9]  += v2.y; pd[10] += v2.z; pd[11] += v2.w;
            pd[12] += v3.x; pd[13] += v3.y; pd[14] += v3.z; pd[15] += v3.w;
        }
    }

#pragma unroll
    for (int k = 0; k < DF; k++) {
#pragma unroll
        for (int o = 16; o > 0; o >>= 1) {
            pa[k] += __shfl_down_sync(0xffffffffu, pa[k], o);
            pd[k] += __shfl_down_sync(0xffffffffu, pd[k], o);
        }
    }
    if ((threadIdx.x & 31) == 0) {
#pragma unroll
        for (int k = 0; k < DF; k++) {
            atomicAdd(&s_pa[k], pa[k]);
            atomicAdd(&s_pd[k], pd[k]);
        }
    }
    __syncthreads();
    if (threadIdx.x < DF) {
        atomicAdd(&g_pasum[threadIdx.x], s_pa[threadIdx.x]);
        atomicAdd(&g_pdsum[threadIdx.x], s_pd[threadIdx.x]);
    }
}

// unpack a uint4 (8 halves) into f[8]
__device__ __forceinline__ void h8_to_f(const uint4& u, float* f) {
    const unsigned* p = &u.x;
#pragma unroll
    for (int i = 0; i < 4; i++) {
        float2 t = __half22float2(*(const __half2*)&p[i]);
        f[i * 2 + 0] = t.x; f[i * 2 + 1] = t.y;
    }
}
// load 4 fp16 weights from shared, convert to fp32
__device__ __forceinline__ void ldw4(const __half* base, int idx, float* out) {
    uint2 u = *(const uint2*)(base + idx);
    float2 a = __half22float2(*(const __half2*)&u.x);
    float2 b = __half22float2(*(const __half2*)&u.y);
    out[0] = a.x; out[1] = a.y; out[2] = b.x; out[3] = b.y;
}

// ---- K2: per-node broadcast vectors; fp16 weights in smem ----
__global__ void __launch_bounds__(256) k_node(const float* __restrict__ W,
                                              const float* __restrict__ bias,
                                              int nnz) {
    if (blockIdx.x == 0 && threadIdx.x < DF) {
        int k = threadIdx.x;
        float inv_n = 1.f / (float)NN;
        float inv_e = 1.f / (float)nnz;
        float ds = 0.f, as = 0.f;
#pragma unroll
        for (int j = 0; j < DF; j++) {
            float pdj = g_pdsum[j] * inv_n;
            float paj = g_pasum[j] * inv_e;
            ds += pdj * W[11 * 256 + j * DF + k] + paj * W[13 * 256 + j * DF + k];
            as += pdj * W[12 * 256 + j * DF + k] + paj * W[14 * 256 + j * DF + k];
        }
        g_call[k]  = as + bias[k];
        g_cdiag[k] = ds + bias[DF + k];
    }

    __shared__ __half sWh[9 * DF * DF];  // W2..W10 as fp16
    for (int t = threadIdx.x; t < 9 * DF * DF; t += blockDim.x)
        sWh[t] = __float2half(W[2 * DF * DF + t]);
    __syncthreads();

    int gid = blockIdx.x * blockDim.x + threadIdx.x;
    int n = gid >> 2;
    int q = (gid & 3) * 4;
    if (n >= NN) return;

    float rinv = 1.f / (float)max(g_rcnt[n], 1);
    float cinv = 1.f / (float)max(g_ccnt[n], 1);

    float dv[DF], prv[DF], pcv[DF];
    {
        const float4* dp  = (const float4*)&g_D[(size_t)n * DF];
        *(float4*)&dv[0]  = dp[0];  *(float4*)&dv[4]  = dp[1];
        *(float4*)&dv[8]  = dp[2];  *(float4*)&dv[12] = dp[3];
        const uint4* prp = (const uint4*)(g_PrS_h + (size_t)n * 8);
        const uint4* pcp = (const uint4*)(g_PcS_h + (size_t)n * 8);
        uint4 a = prp[0], b = prp[1], cgl = pcp[0], d = pcp[1];
        h8_to_f(a, &prv[0]); h8_to_f(b, &prv[8]);
        h8_to_f(cgl, &pcv[0]); h8_to_f(d, &pcv[8]);
    }
#pragma unroll
    for (int k = 0; k < DF; k++) { prv[k] *= rinv; pcv[k] *= cinv; }

    float db[4], rb[4], cb[4];
#pragma unroll
    for (int t = 0; t < 4; t++) { db[t] = 0.f; rb[t] = 0.f; cb[t] = 0.f; }

#pragma unroll
    for (int j = 0; j < DF; j++) {
        float d = dv[j], pr = prv[j], pc = pcv[j];
        float w2[4], w3[4], w4[4], w5[4], w6[4], w7[4], w8[4], w9[4], wa[4];
        ldw4(sWh, (0 * DF + j) * DF + q, w2);
        ldw4(sWh, (1 * DF + j) * DF + q, w3);
        ldw4(sWh, (2 * DF + j) * DF + q, w4);
        ldw4(sWh, (3 * DF + j) * DF + q, w5);
        ldw4(sWh, (4 * DF + j) * DF + q, w6);
        ldw4(sWh, (5 * DF + j) * DF + q, w7);
        ldw4(sWh, (6 * DF + j) * DF + q, w8);
        ldw4(sWh, (7 * DF + j) * DF + q, w9);
        ldw4(sWh, (8 * DF + j) * DF + q, wa);
#pragma unroll
        for (int t = 0; t < 4; t++) {
            db[t] += d * w2[t] + pr * w5[t] + pc * w8[t];
            rb[t] += d * w3[t] + pr * w6[t] + pc * w9[t];
            cb[t] += d * w4[t] + pr * w7[t] + pc * wa[t];
        }
    }

    int hidx = n * 8 + (q >> 1);
    __half2 d0 = __floats2half2_rn(db[0], db[1]);
    __half2 d1 = __floats2half2_rn(db[2], db[3]);
    __half2 r0 = __floats2half2_rn(rb[0], rb[1]);
    __half2 r1 = __floats2half2_rn(rb[2], rb[3]);
    __half2 c0 = __floats2half2_rn(cb[0], cb[1]);
    __half2 c1 = __floats2half2_rn(cb[2], cb[3]);
    *(uint2*)&g_diagb_h[hidx] = make_uint2(*(unsigned*)&d0, *(unsigned*)&d1);
    *(uint2*)&g_rowb_h[hidx]  = make_uint2(*(unsigned*)&r0, *(unsigned*)&r1);
    *(uint2*)&g_colb_h[hidx]  = make_uint2(*(unsigned*)&c0, *(unsigned*)&c1);
}

// ---- K3: main per-entry pass, PAIR layout, index-load dedup ----
__global__ void __launch_bounds__(256, 6) k_main(
    const float* __restrict__ vals, const int* __restrict__ row,
    const int* __restrict__ col, const float* __restrict__ W,
    float* __restrict__ Y, int nnz)
{
    __shared__ float sW0[DF * DF];
    __shared__ float scall[DF], scdiag[DF];
    sW0[threadIdx.x] = W[threadIdx.x];  // blockDim == 256
    if (threadIdx.x < DF) {
        scall[threadIdx.x]  = g_call[threadIdx.x];
        scdiag[threadIdx.x] = g_cdiag[threadIdx.x];
    }
    __syncthreads();

    int gid = blockIdx.x * blockDim.x + threadIdx.x;
    int e = gid >> 1;
    if (e >= nnz) return;
    int h = gid & 1;
    int hb = h * 8;
    unsigned mask = __activemask();

    // index dedup: lane h=0 loads row[e], lane h=1 loads col[e]; exchange
    int mine = h ? col[e] : row[e];
    int other = __shfl_xor_sync(mask, mine, 1);
    int r = h ? other : mine;
    int c = h ? mine : other;

    float vo[8];
    {
        const float4* vp = (const float4*)(vals + (size_t)e * DF + hb);
        *(float4*)&vo[0] = vp[0]; *(float4*)&vo[4] = vp[1];
    }
    uint4 rbu = ((const uint4*)(g_rowb_h + (size_t)r * 8))[h];
    uint4 cbu = ((const uint4*)(g_colb_h + (size_t)c * 8))[h];

    float y[8], tmp[8];
#pragma unroll
    for (int k = 0; k < 8; k++) y[k] = scall[hb + k];
    h8_to_f(rbu, tmp);
#pragma unroll
    for (int k = 0; k < 8; k++) y[k] += tmp[k];
    h8_to_f(cbu, tmp);
#pragma unroll
    for (int k = 0; k < 8; k++) y[k] += tmp[k];

    if (r == c) {
        uint4 dbu = ((const uint4*)(g_diagb_h + (size_t)r * 8))[h];
        h8_to_f(dbu, tmp);
#pragma unroll
        for (int k = 0; k < 8; k++) y[k] += tmp[k] + scdiag[hb + k];
    }

    float vx[8];
#pragma unroll
    for (int k = 0; k < 8; k++) vx[k] = __shfl_xor_sync(mask, vo[k], 1);
    float vf[DF];
#pragma unroll
    for (int k = 0; k < 8; k++) {
        vf[k]     = h ? vx[k] : vo[k];
        vf[8 + k] = h ? vo[k] : vx[k];
    }

#pragma unroll
    for (int j = 0; j < DF; j++) {
        float vj = vf[j];
        float4 wA = *(const float4*)&sW0[j * DF + hb];
        float4 wB = *(const float4*)&sW0[j * DF + hb + 4];
        y[0] += vj * wA.x; y[1] += vj * wA.y; y[2] += vj * wA.z; y[3] += vj * wA.w;
        y[4] += vj * wB.x; y[5] += vj * wB.y; y[6] += vj * wB.z; y[7] += vj * wB.w;
    }

    float4* yo = (float4*)(Y + (size_t)e * DF + hb);
    yo[0] = *(float4*)&y[0]; yo[1] = *(float4*)&y[4];
}

// ---- K4: transpose scatter-add, PAIR layout, index-load dedup ----
__global__ void __launch_bounds__(256, 6) k_trans(
    const float* __restrict__ vals, const int* __restrict__ tin,
    const int* __restrict__ tout, const float* __restrict__ W,
    float* __restrict__ Y, int nnzt)
{
    __shared__ float sW1[DF * DF];
    sW1[threadIdx.x] = W[DF * DF + threadIdx.x];  // W[1], blockDim == 256
    __syncthreads();

    int gid = blockIdx.x * blockDim.x + threadIdx.x;
    int t = gid >> 1;
    if (t >= nnzt) return;
    int h = gid & 1;
    int hb = h * 8;
    unsigned mask = __activemask();

    // index dedup: lane h=0 loads tin[t], lane h=1 loads tout[t]; exchange
    int mine = h ? tout[t] : tin[t];
    int other = __shfl_xor_sync(mask, mine, 1);
    int ii = h ? other : mine;
    int io = h ? mine : other;

    float vo[8];
    {
        const float4* vp = (const float4*)(vals + (size_t)ii * DF + hb);
        *(float4*)&vo[0] = vp[0]; *(float4*)&vo[4] = vp[1];
    }
    float vx[8];
#pragma unroll
    for (int k = 0; k < 8; k++) vx[k] = __shfl_xor_sync(mask, vo[k], 1);
    float vf[DF];
#pragma unroll
    for (int k = 0; k < 8; k++) {
        vf[k]     = h ? vx[k] : vo[k];
        vf[8 + k] = h ? vo[k] : vx[k];
    }

    float g[8];
#pragma unroll
    for (int k = 0; k < 8; k++) g[k] = 0.f;
#pragma unroll
    for (int j = 0; j < DF; j++) {
        float vj = vf[j];
        float4 wA = *(const float4*)&sW1[j * DF + hb];
        float4 wB = *(const float4*)&sW1[j * DF + hb + 4];
        g[0] += vj * wA.x; g[1] += vj * wA.y; g[2] += vj * wA.z; g[3] += vj * wA.w;
        g[4] += vj * wB.x; g[5] += vj * wB.y; g[6] += vj * wB.z; g[7] += vj * wB.w;
    }

    float* yp = Y + (size_t)io * DF + hb;
    red4(yp + 0, make_float4(g[0], g[1], g[2], g[3]));
    red4(yp + 4, make_float4(g[4], g[5], g[6], g[7]));
}

extern "C" void kernel_launch(void* const* d_in, const int* in_sizes, int n_in,
                              void* d_out, int out_size) {
    const float* vals = (const float*)d_in[0];
    const float* W    = (const float*)d_in[1];
    const float* bias = (const float*)d_in[2];
    const int* row    = (const int*)d_in[3];
    const int* col    = (const int*)d_in[4];
    const int* tin    = (const int*)d_in[5];
    const int* tout   = (const int*)d_in[6];
    float* Y = (float*)d_out;

    int nnz  = in_sizes[0] / DF;
    int nnzt = in_sizes[5];

    k_zero<<<1024, 256>>>();
    k_pool<<<2368, 256>>>(vals, row, col, nnz);
    k_node<<<(NN * 4 + 255) / 256, 256>>>(W, bias, nnz);
    k_main<<<(nnz * 2 + 255) / 256, 256>>>(vals, row, col, W, Y, nnz);
    k_trans<<<(nnzt * 2 + 255) / 256, 256>>>(vals, tin, tout, W, Y, nnzt);
}